// round 11
// baseline (speedup 1.0000x reference)
#include <cuda_runtime.h>
#include <cuda_bf16.h>
#include <cstdint>

typedef unsigned long long u64;
typedef unsigned int u32;
typedef unsigned short u16;

// ---------------- problem-size constants ----------------
#define MAX_NODES 100000
#define MAX_EDGES 1000000
#define FEAT      64
#define SCAN_BLK  1024
#define MAX_SCAN_BLOCKS ((MAX_NODES + SCAN_BLK - 1) / SCAN_BLK)   // 98

// ---------------- device scratch ----------------
struct ZeroRegion {
    int deg[MAX_NODES];
    u32 status[MAX_SCAN_BLOCKS];
};
__device__ ZeroRegion g_zz;
__device__ int   g_off[MAX_NODES + 1];
__device__ int   g_cur[MAX_NODES];
__device__ int   g_sorted[MAX_EDGES];
// zy[row][0..63] = x@W_self + b ; zy[row][64..127] = x@W_neigh
__device__ float g_zy[(size_t)MAX_NODES * 128];

#define FLAG_AGG    (1u << 30)
#define FLAG_PREFIX (2u << 30)
#define VAL_MASK    0x3FFFFFFFu

// ---------------- packed f32x2 helpers ----------------
__device__ __forceinline__ u64 f32x2_add(u64 a, u64 b) {
    u64 d; asm("add.rn.f32x2 %0, %1, %2;" : "=l"(d) : "l"(a), "l"(b)); return d;
}
__device__ __forceinline__ void f32x2_unpack(u64 v, float& lo, float& hi) {
    asm("mov.b64 {%0, %1}, %2;" : "=f"(lo), "=f"(hi) : "l"(v));
}

__device__ __forceinline__ u16 f2bf(float f) {
    __nv_bfloat16 h = __float2bfloat16_rn(f);
    return *reinterpret_cast<u16*>(&h);
}
__device__ __forceinline__ float bf2f(u16 b) {
    return __uint_as_float(((u32)b) << 16);
}

// ---------------- 1) degree histogram (4 edges / thread) ----------------
__global__ void k_hist(const int* __restrict__ dst, int n_edges) {
    int q = blockIdx.x * blockDim.x + threadIdx.x;
    int e = q * 4;
    if (e + 3 < n_edges) {
        int4 d = *(const int4*)(dst + e);
        atomicAdd(&g_zz.deg[d.x], 1);
        atomicAdd(&g_zz.deg[d.y], 1);
        atomicAdd(&g_zz.deg[d.z], 1);
        atomicAdd(&g_zz.deg[d.w], 1);
    } else {
        for (; e < n_edges; e++) atomicAdd(&g_zz.deg[dst[e]], 1);
    }
}

// ---------------- 2) scan (decoupled lookback) ----------------
__global__ __launch_bounds__(SCAN_BLK) void k_scan(int n, int n_edges) {
    __shared__ int ws[32];
    __shared__ int sPrefix;

    int tile = blockIdx.x;
    int i    = tile * SCAN_BLK + threadIdx.x;
    int lane = threadIdx.x & 31;
    int wid  = threadIdx.x >> 5;

    int v    = (i < n) ? g_zz.deg[i] : 0;
    int orig = v;
    #pragma unroll
    for (int o = 1; o < 32; o <<= 1) {
        int t = __shfl_up_sync(0xffffffffu, v, o);
        if (lane >= o) v += t;
    }
    if (lane == 31) ws[wid] = v;
    __syncthreads();
    if (wid == 0) {
        int w = ws[lane];
        #pragma unroll
        for (int o = 1; o < 32; o <<= 1) {
            int t = __shfl_up_sync(0xffffffffu, w, o);
            if (lane >= o) w += t;
        }
        ws[lane] = w;
    }
    __syncthreads();
    int base  = wid ? ws[wid - 1] : 0;
    int total = ws[31];

    if (wid == 0) {
        if (tile == 0) {
            if (lane == 0) {
                atomicExch(&g_zz.status[0], FLAG_PREFIX | (u32)total);
                sPrefix = 0;
            }
        } else {
            if (lane == 0)
                atomicExch(&g_zz.status[tile], FLAG_AGG | (u32)total);

            int prefix = 0;
            int base_t = tile - 1;
            while (base_t >= 0) {
                int t = base_t - lane;
                u32 s = 0;
                if (t >= 0) {
                    do { s = *(volatile u32*)&g_zz.status[t]; } while ((s >> 30) == 0u);
                }
                unsigned pm = __ballot_sync(0xffffffffu, t >= 0 && ((s >> 30) == 2u));
                int val = (int)(s & VAL_MASK);
                if (pm) {
                    int firstP  = __ffs(pm) - 1;
                    int contrib = (lane <= firstP) ? val : 0;
                    #pragma unroll
                    for (int o = 16; o; o >>= 1)
                        contrib += __shfl_xor_sync(0xffffffffu, contrib, o);
                    prefix += contrib;
                    break;
                } else {
                    int contrib = (t >= 0) ? val : 0;
                    #pragma unroll
                    for (int o = 16; o; o >>= 1)
                        contrib += __shfl_xor_sync(0xffffffffu, contrib, o);
                    prefix += contrib;
                    base_t -= 32;
                }
            }
            if (lane == 0) {
                atomicExch(&g_zz.status[tile], FLAG_PREFIX | (u32)(prefix + total));
                sPrefix = prefix;
            }
        }
    }
    __syncthreads();

    if (i < n) {
        int o = sPrefix + base + v - orig;
        g_off[i] = o;
        g_cur[i] = o;
    }
    if (tile == gridDim.x - 1 && threadIdx.x == 0) g_off[n] = n_edges;
}

// ---------------- 3) counting-sort scatter ----------------
__global__ void k_scatter(const int* __restrict__ src, const int* __restrict__ dst,
                          int n_edges) {
    int q = blockIdx.x * blockDim.x + threadIdx.x;
    int e = q * 4;
    if (e + 3 < n_edges) {
        int4 d = *(const int4*)(dst + e);
        int4 s = *(const int4*)(src + e);
        g_sorted[atomicAdd(&g_cur[d.x], 1)] = s.x;
        g_sorted[atomicAdd(&g_cur[d.y], 1)] = s.y;
        g_sorted[atomicAdd(&g_cur[d.z], 1)] = s.z;
        g_sorted[atomicAdd(&g_cur[d.w], 1)] = s.w;
    } else {
        for (; e < n_edges; e++)
            g_sorted[atomicAdd(&g_cur[dst[e]], 1)] = src[e];
    }
}

// ---------------- 4) bf16-split HMMA GEMM: zy = [x@Ws + b | x@Wn] ----------------
// 128 threads (4 warps), tile 64 rows x 128 cols, K=64 fp32.
// Split: x = hi + lo (bf16 each); W likewise. D = Ahi@Whi + Ahi@Wlo + Alo@Whi.
// mma.sync.m16n8k16 bf16; warp w owns rows w*16..w*16+15, all 128 cols.
// smem pitch 72 bf16 (=144B, ≡16 mod 128) -> fragment loads bank-conflict-free.
#define AP 72
__global__ __launch_bounds__(128) void k_gemm_mma(
    const float* __restrict__ x,
    const float* __restrict__ Ws,
    const float* __restrict__ Wn,
    const float* __restrict__ bias,
    int n)
{
    __shared__ u16 sAhi[64][AP];
    __shared__ u16 sAlo[64][AP];
    __shared__ u16 sBhi[128][AP];
    __shared__ u16 sBlo[128][AP];
    __shared__ float sB64[64];

    int tid  = threadIdx.x;
    int wid  = tid >> 5;
    int lane = tid & 31;
    int r0   = blockIdx.x * 64;

    if (tid < 64) sB64[tid] = bias[tid];

    // fill B: row n' (0..127) = [Ws col | Wn col], k contiguous
    for (int i = tid; i < 8192; i += 128) {
        int k  = i >> 7;           // 0..63
        int nn = i & 127;          // 0..127; consecutive threads -> coalesced
        float w = (nn < 64) ? __ldg(&Ws[k * 64 + nn]) : __ldg(&Wn[k * 64 + (nn - 64)]);
        u16 h = f2bf(w);
        u16 l = f2bf(w - bf2f(h));
        sBhi[nn][k] = h;
        sBlo[nn][k] = l;
    }

    // fill A: 64 rows x 64 k (hi + lo)
    for (int i = tid; i < 1024; i += 128) {
        int r  = i >> 4;
        int c4 = i & 15;
        int gr = r0 + r;
        float4 v = make_float4(0.f, 0.f, 0.f, 0.f);
        if (gr < n) v = ((const float4*)x)[(size_t)gr * 16 + c4];
        int k = c4 * 4;
        u16 h0 = f2bf(v.x), h1 = f2bf(v.y), h2 = f2bf(v.z), h3 = f2bf(v.w);
        sAhi[r][k]     = h0; sAlo[r][k]     = f2bf(v.x - bf2f(h0));
        sAhi[r][k + 1] = h1; sAlo[r][k + 1] = f2bf(v.y - bf2f(h1));
        sAhi[r][k + 2] = h2; sAlo[r][k + 2] = f2bf(v.z - bf2f(h2));
        sAhi[r][k + 3] = h3; sAlo[r][k + 3] = f2bf(v.w - bf2f(h3));
    }
    __syncthreads();

    int rbase = wid * 16;
    int rq    = lane >> 2;        // 0..7
    int kq    = (lane & 3) * 2;   // 0,2,4,6

    float d[16][4];
    #pragma unroll
    for (int t = 0; t < 16; t++)
        #pragma unroll
        for (int c = 0; c < 4; c++) d[t][c] = 0.f;

    // 3 terms x 4 ksteps of 16
    #pragma unroll
    for (int term = 0; term < 3; term++) {
        const u16 (*A)[AP] = (term == 2) ? sAlo : sAhi;
        const u16 (*B)[AP] = (term == 1) ? sBlo : sBhi;
        #pragma unroll
        for (int ks = 0; ks < 4; ks++) {
            int k0 = ks * 16;
            u32 a0 = *(const u32*)&A[rbase + rq][k0 + kq];
            u32 a1 = *(const u32*)&A[rbase + rq + 8][k0 + kq];
            u32 a2 = *(const u32*)&A[rbase + rq][k0 + 8 + kq];
            u32 a3 = *(const u32*)&A[rbase + rq + 8][k0 + 8 + kq];
            #pragma unroll
            for (int t = 0; t < 16; t++) {
                int n0 = t * 8;
                u32 b0 = *(const u32*)&B[n0 + rq][k0 + kq];
                u32 b1 = *(const u32*)&B[n0 + rq][k0 + 8 + kq];
                asm volatile(
                    "mma.sync.aligned.m16n8k16.row.col.f32.bf16.bf16.f32 "
                    "{%0,%1,%2,%3}, {%4,%5,%6,%7}, {%8,%9}, {%0,%1,%2,%3};"
                    : "+f"(d[t][0]), "+f"(d[t][1]), "+f"(d[t][2]), "+f"(d[t][3])
                    : "r"(a0), "r"(a1), "r"(a2), "r"(a3), "r"(b0), "r"(b1));
            }
        }
    }

    // epilogue: d[t][0,1] -> (row rbase+rq, cols t*8+kq, +1); d[t][2,3] -> row+8
    int gr0 = r0 + rbase + rq;
    int gr1 = gr0 + 8;
    #pragma unroll
    for (int t = 0; t < 16; t++) {
        int col = t * 8 + kq;
        float bx = (col < 64) ? sB64[col]     : 0.f;
        float by = (col < 64) ? sB64[col + 1] : 0.f;
        if (gr0 < n) {
            float2 o0 = make_float2(d[t][0] + bx, d[t][1] + by);
            *(float2*)&g_zy[(size_t)gr0 * 128 + col] = o0;
        }
        if (gr1 < n) {
            float2 o1 = make_float2(d[t][2] + bx, d[t][3] + by);
            *(float2*)&g_zy[(size_t)gr1 * 128 + col] = o1;
        }
    }
}

// ---------------- 5) aggregation: one warp per dst, float4 half-warp (R9) ----------------
__global__ __launch_bounds__(256) void k_aggregate(float* __restrict__ out, int num_dst) {
    int warp = (blockIdx.x * blockDim.x + threadIdx.x) >> 5;
    int lane = threadIdx.x & 31;
    if (warp >= num_dst) return;

    int fl = lane & 15;
    int h  = lane >> 4;

    int beg = g_off[warp];
    int end = g_off[warp + 1];

    u64 a00 = 0ull, a01 = 0ull;
    u64 a10 = 0ull, a11 = 0ull;

    int j = beg;
    for (; j + 3 < end; j += 4) {
        int sa = g_sorted[j + h];
        int sb = g_sorted[j + 2 + h];
        float4 va = *(const float4*)(g_zy + (size_t)sa * 128 + 64 + fl * 4);
        float4 vb = *(const float4*)(g_zy + (size_t)sb * 128 + 64 + fl * 4);
        const u64* pa = (const u64*)&va;
        const u64* pb = (const u64*)&vb;
        a00 = f32x2_add(a00, pa[0]);
        a01 = f32x2_add(a01, pa[1]);
        a10 = f32x2_add(a10, pb[0]);
        a11 = f32x2_add(a11, pb[1]);
    }
    for (; j < end; j += 2) {
        if (j + h < end) {
            int s = g_sorted[j + h];
            float4 v = *(const float4*)(g_zy + (size_t)s * 128 + 64 + fl * 4);
            const u64* p = (const u64*)&v;
            a00 = f32x2_add(a00, p[0]);
            a01 = f32x2_add(a01, p[1]);
        }
    }
    a00 = f32x2_add(a00, a10);
    a01 = f32x2_add(a01, a11);
    a00 = f32x2_add(a00, __shfl_xor_sync(0xffffffffu, a00, 16));
    a01 = f32x2_add(a01, __shfl_xor_sync(0xffffffffu, a01, 16));

    int deg = end - beg;
    float inv = 1.0f / (float)(deg > 0 ? deg : 1);

    if (h == 0) {
        float s0, s1, s2, s3;
        f32x2_unpack(a00, s0, s1);
        f32x2_unpack(a01, s2, s3);
        float4 z = *(const float4*)(g_zy + (size_t)warp * 128 + fl * 4);
        float4 o;
        o.x = fmaxf(z.x + s0 * inv, 0.f);
        o.y = fmaxf(z.y + s1 * inv, 0.f);
        o.z = fmaxf(z.z + s2 * inv, 0.f);
        o.w = fmaxf(z.w + s3 * inv, 0.f);
        *(float4*)(out + (size_t)warp * 64 + fl * 4) = o;
    }
}

// ---------------- launch ----------------
extern "C" void kernel_launch(void* const* d_in, const int* in_sizes, int n_in,
                              void* d_out, int out_size) {
    const float* x  = (const float*)d_in[0];
    const float* Ws = (const float*)d_in[1];
    const float* Wn = (const float*)d_in[2];
    const float* b  = (const float*)d_in[3];
    const int*   src = (const int*)d_in[4];
    const int*   dst = (const int*)d_in[5];

    int n_src   = in_sizes[0] / FEAT;
    int n_edges = in_sizes[4];
    int num_dst = out_size / FEAT;
    float* out  = (float*)d_out;

    static cudaStream_t s_gemm  = nullptr;
    static cudaEvent_t  ev_fork = nullptr;
    static cudaEvent_t  ev_join = nullptr;
    static void*        p_zz    = nullptr;
    if (s_gemm == nullptr) {
        cudaStreamCreateWithFlags(&s_gemm, cudaStreamNonBlocking);
        cudaEventCreateWithFlags(&ev_fork, cudaEventDisableTiming);
        cudaEventCreateWithFlags(&ev_join, cudaEventDisableTiming);
        cudaGetSymbolAddress(&p_zz, g_zz);
    }

    // fork: HMMA GEMM on side stream
    cudaEventRecord(ev_fork, 0);
    cudaStreamWaitEvent(s_gemm, ev_fork, 0);
    int gemm_blocks = (n_src + 63) / 64;
    k_gemm_mma<<<gemm_blocks, 128, 0, s_gemm>>>(x, Ws, Wn, b, n_src);
    cudaEventRecord(ev_join, s_gemm);

    // CSR build chain: memset -> hist -> scan -> scatter
    cudaMemsetAsync(p_zz, 0, sizeof(ZeroRegion), 0);

    int tb = 256;
    int quads    = (n_edges + 3) / 4;
    int gb_quads = (quads + tb - 1) / tb;
    int nb_scan  = (num_dst + SCAN_BLK - 1) / SCAN_BLK;

    k_hist<<<gb_quads, tb>>>(dst, n_edges);
    k_scan<<<nb_scan, SCAN_BLK>>>(num_dst, n_edges);
    k_scatter<<<gb_quads, tb>>>(src, dst, n_edges);

    // join: aggregate needs both CSR and zy
    cudaStreamWaitEvent(0, ev_join, 0);
    int agg_blocks = (num_dst * 32 + 255) / 256;
    k_aggregate<<<agg_blocks, 256>>>(out, num_dst);
}

// round 13
// speedup vs baseline: 1.1407x; 1.1407x over previous
#include <cuda_runtime.h>
#include <cstdint>

typedef unsigned long long u64;
typedef unsigned int u32;

// ---------------- problem-size constants ----------------
#define MAX_NODES 100000
#define MAX_EDGES 1000000
#define FEAT      64
#define SCAN_BLK  1024
#define MAX_SCAN_BLOCKS ((MAX_NODES + SCAN_BLK - 1) / SCAN_BLK)   // 98

// ---------------- device scratch ----------------
struct ZeroRegion {
    int deg[MAX_NODES];
    u32 status[MAX_SCAN_BLOCKS];
};
__device__ ZeroRegion g_zz;
__device__ int   g_off[MAX_NODES + 1];
__device__ int   g_cur[MAX_NODES];
__device__ int   g_sorted[MAX_EDGES];
// zy[row][0..63] = x@W_self + b ; zy[row][64..127] = x@W_neigh
__device__ float g_zy[(size_t)MAX_NODES * 128];

#define FLAG_AGG    (1u << 30)
#define FLAG_PREFIX (2u << 30)
#define VAL_MASK    0x3FFFFFFFu

// ---------------- packed f32x2 helpers (Blackwell FFMA2) ----------------
__device__ __forceinline__ u64 f32x2_dup(float a) {
    u64 r; asm("mov.b64 %0, {%1, %1};" : "=l"(r) : "f"(a)); return r;
}
__device__ __forceinline__ u64 f32x2_fma(u64 a, u64 b, u64 c) {
    u64 d; asm("fma.rn.f32x2 %0, %1, %2, %3;" : "=l"(d) : "l"(a), "l"(b), "l"(c)); return d;
}
__device__ __forceinline__ u64 f32x2_add(u64 a, u64 b) {
    u64 d; asm("add.rn.f32x2 %0, %1, %2;" : "=l"(d) : "l"(a), "l"(b)); return d;
}
__device__ __forceinline__ void f32x2_unpack(u64 v, float& lo, float& hi) {
    asm("mov.b64 {%0, %1}, %2;" : "=f"(lo), "=f"(hi) : "l"(v));
}

// ---------------- 1) degree histogram (4 edges / thread) ----------------
__global__ void k_hist(const int* __restrict__ dst, int n_edges) {
    int q = blockIdx.x * blockDim.x + threadIdx.x;
    int e = q * 4;
    if (e + 3 < n_edges) {
        int4 d = *(const int4*)(dst + e);
        atomicAdd(&g_zz.deg[d.x], 1);
        atomicAdd(&g_zz.deg[d.y], 1);
        atomicAdd(&g_zz.deg[d.z], 1);
        atomicAdd(&g_zz.deg[d.w], 1);
    } else {
        for (; e < n_edges; e++) atomicAdd(&g_zz.deg[dst[e]], 1);
    }
}

// ---------------- 2) scan (decoupled lookback) ----------------
__global__ __launch_bounds__(SCAN_BLK) void k_scan(int n, int n_edges) {
    __shared__ int ws[32];
    __shared__ int sPrefix;

    int tile = blockIdx.x;
    int i    = tile * SCAN_BLK + threadIdx.x;
    int lane = threadIdx.x & 31;
    int wid  = threadIdx.x >> 5;

    int v    = (i < n) ? g_zz.deg[i] : 0;
    int orig = v;
    #pragma unroll
    for (int o = 1; o < 32; o <<= 1) {
        int t = __shfl_up_sync(0xffffffffu, v, o);
        if (lane >= o) v += t;
    }
    if (lane == 31) ws[wid] = v;
    __syncthreads();
    if (wid == 0) {
        int w = ws[lane];
        #pragma unroll
        for (int o = 1; o < 32; o <<= 1) {
            int t = __shfl_up_sync(0xffffffffu, w, o);
            if (lane >= o) w += t;
        }
        ws[lane] = w;
    }
    __syncthreads();
    int base  = wid ? ws[wid - 1] : 0;
    int total = ws[31];

    if (wid == 0) {
        if (tile == 0) {
            if (lane == 0) {
                atomicExch(&g_zz.status[0], FLAG_PREFIX | (u32)total);
                sPrefix = 0;
            }
        } else {
            if (lane == 0)
                atomicExch(&g_zz.status[tile], FLAG_AGG | (u32)total);

            int prefix = 0;
            int base_t = tile - 1;
            while (base_t >= 0) {
                int t = base_t - lane;
                u32 s = 0;
                if (t >= 0) {
                    do { s = *(volatile u32*)&g_zz.status[t]; } while ((s >> 30) == 0u);
                }
                unsigned pm = __ballot_sync(0xffffffffu, t >= 0 && ((s >> 30) == 2u));
                int val = (int)(s & VAL_MASK);
                if (pm) {
                    int firstP  = __ffs(pm) - 1;
                    int contrib = (lane <= firstP) ? val : 0;
                    #pragma unroll
                    for (int o = 16; o; o >>= 1)
                        contrib += __shfl_xor_sync(0xffffffffu, contrib, o);
                    prefix += contrib;
                    break;
                } else {
                    int contrib = (t >= 0) ? val : 0;
                    #pragma unroll
                    for (int o = 16; o; o >>= 1)
                        contrib += __shfl_xor_sync(0xffffffffu, contrib, o);
                    prefix += contrib;
                    base_t -= 32;
                }
            }
            if (lane == 0) {
                atomicExch(&g_zz.status[tile], FLAG_PREFIX | (u32)(prefix + total));
                sPrefix = prefix;
            }
        }
    }
    __syncthreads();

    if (i < n) {
        int o = sPrefix + base + v - orig;
        g_off[i] = o;
        g_cur[i] = o;
    }
    if (tile == gridDim.x - 1 && threadIdx.x == 0) g_off[n] = n_edges;
}

// ---------------- 3) counting-sort scatter (4 edges / thread) ----------------
__global__ void k_scatter(const int* __restrict__ src, const int* __restrict__ dst,
                          int n_edges) {
    int q = blockIdx.x * blockDim.x + threadIdx.x;
    int e = q * 4;
    if (e + 3 < n_edges) {
        int4 d = *(const int4*)(dst + e);
        int4 s = *(const int4*)(src + e);
        g_sorted[atomicAdd(&g_cur[d.x], 1)] = s.x;
        g_sorted[atomicAdd(&g_cur[d.y], 1)] = s.y;
        g_sorted[atomicAdd(&g_cur[d.z], 1)] = s.z;
        g_sorted[atomicAdd(&g_cur[d.w], 1)] = s.w;
    } else {
        for (; e < n_edges; e++)
            g_sorted[atomicAdd(&g_cur[dst[e]], 1)] = src[e];
    }
}

// ---------------- 4) zy = [ x@W_self + b | x@W_neigh ], FFMA2, 32x32 warp tiles ----------------
// 256 threads, block tile 64 rows x 128 cols, K=64.
// Warp w (0..7): rows (w>>2)*32 .. +31, cols (w&3)*32 .. +31 (square tile ->
// minimum smem crossbar traffic: 256B/warp/k vs 544B for the 8x128 mapping).
// Lane: rowgroup (lane>>3)*8 (broadcast across 8 lanes), colgroup (lane&7)*4
// (8 distinct float4 = one contiguous 128B request).
#define XT_PITCH 66
__global__ __launch_bounds__(256) void k_gemm_zy(
    const float* __restrict__ x,
    const float* __restrict__ Ws,
    const float* __restrict__ Wn,
    const float* __restrict__ b,
    int n)
{
    __shared__ float sXT[64][XT_PITCH];   // transposed: sXT[k][row]
    __shared__ float sW[64][128];
    __shared__ float sB[64];

    int tid = threadIdx.x;
    int r0  = blockIdx.x * 64;

    for (int i = tid; i < 2048; i += 256) {
        int k  = i >> 5;
        int c4 = i & 31;
        float4 v = (c4 < 16) ? ((const float4*)Ws)[k * 16 + c4]
                             : ((const float4*)Wn)[k * 16 + (c4 - 16)];
        ((float4*)&sW[k][0])[c4] = v;
    }
    if (tid < 64) sB[tid] = b[tid];

    for (int i = tid; i < 1024; i += 256) {
        int r  = i >> 4;
        int c4 = i & 15;
        int gr = r0 + r;
        float4 v = make_float4(0.f, 0.f, 0.f, 0.f);
        if (gr < n) v = ((const float4*)x)[(size_t)gr * 16 + c4];
        int k = c4 * 4;
        sXT[k + 0][r] = v.x;
        sXT[k + 1][r] = v.y;
        sXT[k + 2][r] = v.z;
        sXT[k + 3][r] = v.w;
    }
    __syncthreads();

    int w  = tid >> 5;
    int wl = tid & 31;
    int cg = (w & 3) * 32 + (wl & 7) * 4;    // 4 output columns
    int rg = (w >> 2) * 32 + (wl >> 3) * 8;  // 8 output rows = 4 row-pairs

    u64 acc[4][4];
    #pragma unroll
    for (int t = 0; t < 4; t++)
        #pragma unroll
        for (int c = 0; c < 4; c++) acc[t][c] = 0ull;

    #pragma unroll 8
    for (int k = 0; k < 64; k++) {
        u64 a2[4];
        #pragma unroll
        for (int t = 0; t < 4; t++)
            a2[t] = *(const u64*)&sXT[k][rg + 2 * t];

        float4 wv = *(const float4*)&sW[k][cg];
        u64 w0 = f32x2_dup(wv.x);
        u64 w1 = f32x2_dup(wv.y);
        u64 w2 = f32x2_dup(wv.z);
        u64 w3 = f32x2_dup(wv.w);

        #pragma unroll
        for (int t = 0; t < 4; t++) {
            acc[t][0] = f32x2_fma(a2[t], w0, acc[t][0]);
            acc[t][1] = f32x2_fma(a2[t], w1, acc[t][1]);
            acc[t][2] = f32x2_fma(a2[t], w2, acc[t][2]);
            acc[t][3] = f32x2_fma(a2[t], w3, acc[t][3]);
        }
    }

    float4 bias = make_float4(0.f, 0.f, 0.f, 0.f);
    if (cg < 64) bias = *(const float4*)&sB[cg];

    #pragma unroll
    for (int t = 0; t < 4; t++) {
        float lo[4], hi[4];
        #pragma unroll
        for (int c = 0; c < 4; c++) f32x2_unpack(acc[t][c], lo[c], hi[c]);
        int gr0 = r0 + rg + 2 * t;
        if (gr0 < n) {
            float4 o0 = make_float4(lo[0] + bias.x, lo[1] + bias.y,
                                    lo[2] + bias.z, lo[3] + bias.w);
            *(float4*)&g_zy[(size_t)gr0 * 128 + cg] = o0;
        }
        if (gr0 + 1 < n) {
            float4 o1 = make_float4(hi[0] + bias.x, hi[1] + bias.y,
                                    hi[2] + bias.z, hi[3] + bias.w);
            *(float4*)&g_zy[(size_t)(gr0 + 1) * 128 + cg] = o1;
        }
    }
}

// ---------------- 5) aggregation: one warp per dst, float4 half-warp (R9) ----------------
__global__ __launch_bounds__(256) void k_aggregate(float* __restrict__ out, int num_dst) {
    int warp = (blockIdx.x * blockDim.x + threadIdx.x) >> 5;
    int lane = threadIdx.x & 31;
    if (warp >= num_dst) return;

    int fl = lane & 15;
    int h  = lane >> 4;

    int beg = g_off[warp];
    int end = g_off[warp + 1];

    u64 a00 = 0ull, a01 = 0ull;
    u64 a10 = 0ull, a11 = 0ull;

    int j = beg;
    for (; j + 3 < end; j += 4) {
        int sa = g_sorted[j + h];
        int sb = g_sorted[j + 2 + h];
        float4 va = *(const float4*)(g_zy + (size_t)sa * 128 + 64 + fl * 4);
        float4 vb = *(const float4*)(g_zy + (size_t)sb * 128 + 64 + fl * 4);
        const u64* pa = (const u64*)&va;
        const u64* pb = (const u64*)&vb;
        a00 = f32x2_add(a00, pa[0]);
        a01 = f32x2_add(a01, pa[1]);
        a10 = f32x2_add(a10, pb[0]);
        a11 = f32x2_add(a11, pb[1]);
    }
    for (; j < end; j += 2) {
        if (j + h < end) {
            int s = g_sorted[j + h];
            float4 v = *(const float4*)(g_zy + (size_t)s * 128 + 64 + fl * 4);
            const u64* p = (const u64*)&v;
            a00 = f32x2_add(a00, p[0]);
            a01 = f32x2_add(a01, p[1]);
        }
    }
    a00 = f32x2_add(a00, a10);
    a01 = f32x2_add(a01, a11);
    a00 = f32x2_add(a00, __shfl_xor_sync(0xffffffffu, a00, 16));
    a01 = f32x2_add(a01, __shfl_xor_sync(0xffffffffu, a01, 16));

    int deg = end - beg;
    float inv = 1.0f / (float)(deg > 0 ? deg : 1);

    if (h == 0) {
        float s0, s1, s2, s3;
        f32x2_unpack(a00, s0, s1);
        f32x2_unpack(a01, s2, s3);
        float4 z = *(const float4*)(g_zy + (size_t)warp * 128 + fl * 4);
        float4 o;
        o.x = fmaxf(z.x + s0 * inv, 0.f);
        o.y = fmaxf(z.y + s1 * inv, 0.f);
        o.z = fmaxf(z.z + s2 * inv, 0.f);
        o.w = fmaxf(z.w + s3 * inv, 0.f);
        *(float4*)(out + (size_t)warp * 64 + fl * 4) = o;
    }
}

// ---------------- launch ----------------
extern "C" void kernel_launch(void* const* d_in, const int* in_sizes, int n_in,
                              void* d_out, int out_size) {
    const float* x  = (const float*)d_in[0];
    const float* Ws = (const float*)d_in[1];
    const float* Wn = (const float*)d_in[2];
    const float* b  = (const float*)d_in[3];
    const int*   src = (const int*)d_in[4];
    const int*   dst = (const int*)d_in[5];

    int n_src   = in_sizes[0] / FEAT;
    int n_edges = in_sizes[4];
    int num_dst = out_size / FEAT;
    float* out  = (float*)d_out;

    static cudaStream_t s_gemm  = nullptr;
    static cudaEvent_t  ev_fork = nullptr;
    static cudaEvent_t  ev_join = nullptr;
    static void*        p_zz    = nullptr;
    if (s_gemm == nullptr) {
        cudaStreamCreateWithFlags(&s_gemm, cudaStreamNonBlocking);
        cudaEventCreateWithFlags(&ev_fork, cudaEventDisableTiming);
        cudaEventCreateWithFlags(&ev_join, cudaEventDisableTiming);
        cudaGetSymbolAddress(&p_zz, g_zz);
    }

    // fork: GEMM on side stream
    cudaEventRecord(ev_fork, 0);
    cudaStreamWaitEvent(s_gemm, ev_fork, 0);
    int gemm_blocks = (n_src + 63) / 64;
    k_gemm_zy<<<gemm_blocks, 256, 0, s_gemm>>>(x, Ws, Wn, b, n_src);
    cudaEventRecord(ev_join, s_gemm);

    // CSR build chain: memset -> hist -> scan -> scatter
    cudaMemsetAsync(p_zz, 0, sizeof(ZeroRegion), 0);

    int tb = 256;
    int quads    = (n_edges + 3) / 4;
    int gb_quads = (quads + tb - 1) / tb;
    int nb_scan  = (num_dst + SCAN_BLK - 1) / SCAN_BLK;

    k_hist<<<gb_quads, tb>>>(dst, n_edges);
    k_scan<<<nb_scan, SCAN_BLK>>>(num_dst, n_edges);
    k_scatter<<<gb_quads, tb>>>(src, dst, n_edges);

    // join: aggregate needs both CSR and zy
    cudaStreamWaitEvent(0, ev_join, 0);
    int agg_blocks = (num_dst * 32 + 255) / 256;
    k_aggregate<<<agg_blocks, 256>>>(out, num_dst);
}